// round 6
// baseline (speedup 1.0000x reference)
#include <cuda_runtime.h>
#include <cuda_fp16.h>
#include <cstdint>

// ColBERT MaxSim on GB300 (sm_103): mma.sync f16 (f16 accum), 4 ILP chains, cp.async.
// qs: (64, 32, 128) fp32 ; ps: (64, 1024, 128) fp32 ; out: (64, 64) fp32
// out[b,c] = sum_n max_s dot(qs[b,n,:], ps[c,s,:])

#define NQ       64
#define TQ       32
#define ND       64
#define TS       1024
#define DIM      128
#define G_Q      4                    // queries per CTA (1 per warp)
#define THREADS  128
#define SN       64                   // doc tokens per chunk
#define NCHUNK   (TS / SN)            // 16
#define ROWB     256                  // bytes per token row in smem (128 f16)
#define BUFB     (SN * ROWB)          // 16 KB per buffer

// fp16 ps scratch (device-global; allocation-free per harness rules)
__device__ uint4 scratch_ps_v[(size_t)ND * TS * DIM / 8];   // 16 MB

__global__ void cvt_ps_kernel(const float4* __restrict__ src) {
    int i = blockIdx.x * blockDim.x + threadIdx.x;
    float4 a = src[2 * i], b = src[2 * i + 1];
    uint4 o;
    __half2 h;
    h = __floats2half2_rn(a.x, a.y); o.x = *reinterpret_cast<uint32_t*>(&h);
    h = __floats2half2_rn(a.z, a.w); o.y = *reinterpret_cast<uint32_t*>(&h);
    h = __floats2half2_rn(b.x, b.y); o.z = *reinterpret_cast<uint32_t*>(&h);
    h = __floats2half2_rn(b.z, b.w); o.w = *reinterpret_cast<uint32_t*>(&h);
    scratch_ps_v[i] = o;
}

__device__ __forceinline__ uint32_t smem_u32(const void* p) {
    uint32_t a;
    asm("{ .reg .u64 t; cvta.to.shared.u64 t, %1; cvt.u32.u64 %0, t; }" : "=r"(a) : "l"(p));
    return a;
}

__device__ __forceinline__ unsigned pack_h2(float lo, float hi) {
    __half2 h = __floats2half2_rn(lo, hi);
    return *reinterpret_cast<unsigned*>(&h);
}

// m16n8k16, f16 inputs, f16 accumulators (d,c packed as 2x half2 regs)
__device__ __forceinline__ void mma_f16acc(unsigned& d0, unsigned& d1,
                                           unsigned a0, unsigned a1, unsigned a2, unsigned a3,
                                           unsigned b0, unsigned b1) {
    asm volatile(
        "mma.sync.aligned.m16n8k16.row.col.f16.f16.f16.f16 "
        "{%0,%1}, {%2,%3,%4,%5}, {%6,%7}, {%0,%1};\n"
        : "+r"(d0), "+r"(d1)
        : "r"(a0), "r"(a1), "r"(a2), "r"(a3), "r"(b0), "r"(b1));
}

__device__ __forceinline__ unsigned hadd2_u(unsigned a, unsigned b) {
    __half2 r = __hadd2(*reinterpret_cast<__half2*>(&a), *reinterpret_cast<__half2*>(&b));
    return *reinterpret_cast<unsigned*>(&r);
}
__device__ __forceinline__ unsigned hmax2_u(unsigned a, unsigned b) {
    __half2 r = __hmax2(*reinterpret_cast<__half2*>(&a), *reinterpret_cast<__half2*>(&b));
    return *reinterpret_cast<unsigned*>(&r);
}
__device__ __forceinline__ float hmax_final(unsigned a) {
    __half2 h = *reinterpret_cast<__half2*>(&a);
    return fmaxf(__low2float(h), __high2float(h));
}

__global__ __launch_bounds__(THREADS, 4)
void colbert_kernel(const float* __restrict__ qs, float* __restrict__ out) {
    __shared__ __align__(1024) char Bs[2 * BUFB];

    const int tid   = threadIdx.x;
    const int w     = tid >> 5;          // warp = query within group
    const int lane  = tid & 31;
    const int g     = lane >> 2;
    const int t     = lane & 3;
    const int c_doc = blockIdx.x;
    const int qg    = blockIdx.y;
    const uint32_t sb = smem_u32(Bs);

    const uint4* gsrc = scratch_ps_v + (size_t)c_doc * TS * DIM / 8;

    // ---- prologue: async-copy chunk 0 into buffer 0 (XOR-swizzled rows) ----
    #pragma unroll
    for (int j = 0; j < 8; j++) {
        int f = j * THREADS + tid;       // 16B unit index, 1024 per chunk
        int r = f >> 4;                  // token row (16 units per 256B row)
        int c = f & 15;                  // 16B chunk within row
        uint32_t dst = sb + r * ROWB + ((c ^ (r & 7)) << 4);
        asm volatile("cp.async.cg.shared.global [%0], [%1], 16;\n" :: "r"(dst), "l"(gsrc + f));
    }
    asm volatile("cp.async.commit_group;\n");

    // ---- A fragments: this warp's query (32 rows x 128 dims), fp32 -> f16 packed ----
    unsigned Af[2][8][4];
    {
        const int rbase = (qg * G_Q + w) * TQ;
        #pragma unroll
        for (int mt = 0; mt < 2; mt++) {
            #pragma unroll
            for (int ks = 0; ks < 8; ks++) {
                const int r0 = rbase + mt * 16 + g;
                const int cc = ks * 16 + t * 2;
                const float2* p0 = reinterpret_cast<const float2*>(qs + (size_t)r0 * DIM + cc);
                const float2* p1 = reinterpret_cast<const float2*>(qs + (size_t)(r0 + 8) * DIM + cc);
                float2 v00 = p0[0];
                float2 v02 = p0[4];
                float2 v10 = p1[0];
                float2 v12 = p1[4];
                Af[mt][ks][0] = pack_h2(v00.x, v00.y);
                Af[mt][ks][1] = pack_h2(v10.x, v10.y);
                Af[mt][ks][2] = pack_h2(v02.x, v02.y);
                Af[mt][ks][3] = pack_h2(v12.x, v12.y);
            }
        }
    }

    // Packed running maxes: rows {g, g+8, g+16, g+24}, cols (2t, 2t+1) as half2
    unsigned rmaxA = 0xFC00FC00u, rmaxB = 0xFC00FC00u;
    unsigned rmaxC = 0xFC00FC00u, rmaxD = 0xFC00FC00u;

    const int rl = lane & 7;             // row provider within 8x8 matrix
    const int mc = lane >> 3;            // which of the 4 matrices this lane addresses

    #pragma unroll 1
    for (int ch = 0; ch < NCHUNK; ch++) {
        asm volatile("cp.async.wait_group 0;\n");
        __syncthreads();

        if (ch + 1 < NCHUNK) {
            const uint4* gs2  = gsrc + (size_t)(ch + 1) * SN * DIM / 8;
            uint32_t     dbuf = sb + ((ch + 1) & 1) * BUFB;
            #pragma unroll
            for (int j = 0; j < 8; j++) {
                int f = j * THREADS + tid;
                int r = f >> 4;
                int c = f & 15;
                uint32_t dst = dbuf + r * ROWB + ((c ^ (r & 7)) << 4);
                asm volatile("cp.async.cg.shared.global [%0], [%1], 16;\n" :: "r"(dst), "l"(gs2 + f));
            }
            asm volatile("cp.async.commit_group;\n");
        }

        // ---- compute on buffer ch&1: 4 independent accumulator chains ----
        const uint32_t cbase = sb + (ch & 1) * BUFB + rl * ROWB;
        #pragma unroll
        for (int nf = 0; nf < 8; nf++) {
            // chains: lo = k[0,64), hi = k[64,128); c0 = rows g/g+8, c1 = rows g+16/g+24
            unsigned c0lo0 = 0, c0lo1 = 0, c0hi0 = 0, c0hi1 = 0;
            unsigned c1lo0 = 0, c1lo1 = 0, c1hi0 = 0, c1hi1 = 0;
            const uint32_t nbase = cbase + nf * 8 * ROWB;
            #pragma unroll
            for (int p = 0; p < 2; p++) {
                // kp pair (p, p+2): lo covers ks {2p, 2p+1}, hi covers ks {2p+4, 2p+5}
                uint32_t addrA = nbase + (((((p    ) << 2) | mc) ^ rl) << 4);
                uint32_t addrB = nbase + (((((p + 2) << 2) | mc) ^ rl) << 4);
                uint32_t bA0, bA1, bA2, bA3, bB0, bB1, bB2, bB3;
                asm volatile("ldmatrix.sync.aligned.m8n8.x4.shared.b16 {%0,%1,%2,%3}, [%4];\n"
                             : "=r"(bA0), "=r"(bA1), "=r"(bA2), "=r"(bA3) : "r"(addrA));
                asm volatile("ldmatrix.sync.aligned.m8n8.x4.shared.b16 {%0,%1,%2,%3}, [%4];\n"
                             : "=r"(bB0), "=r"(bB1), "=r"(bB2), "=r"(bB3) : "r"(addrB));
                mma_f16acc(c0lo0, c0lo1, Af[0][2*p  ][0], Af[0][2*p  ][1], Af[0][2*p  ][2], Af[0][2*p  ][3], bA0, bA1);
                mma_f16acc(c1lo0, c1lo1, Af[1][2*p  ][0], Af[1][2*p  ][1], Af[1][2*p  ][2], Af[1][2*p  ][3], bA0, bA1);
                mma_f16acc(c0hi0, c0hi1, Af[0][2*p+4][0], Af[0][2*p+4][1], Af[0][2*p+4][2], Af[0][2*p+4][3], bB0, bB1);
                mma_f16acc(c1hi0, c1hi1, Af[1][2*p+4][0], Af[1][2*p+4][1], Af[1][2*p+4][2], Af[1][2*p+4][3], bB0, bB1);
                mma_f16acc(c0lo0, c0lo1, Af[0][2*p+1][0], Af[0][2*p+1][1], Af[0][2*p+1][2], Af[0][2*p+1][3], bA2, bA3);
                mma_f16acc(c1lo0, c1lo1, Af[1][2*p+1][0], Af[1][2*p+1][1], Af[1][2*p+1][2], Af[1][2*p+1][3], bA2, bA3);
                mma_f16acc(c0hi0, c0hi1, Af[0][2*p+5][0], Af[0][2*p+5][1], Af[0][2*p+5][2], Af[0][2*p+5][3], bB2, bB3);
                mma_f16acc(c1hi0, c1hi1, Af[1][2*p+5][0], Af[1][2*p+5][1], Af[1][2*p+5][2], Af[1][2*p+5][3], bB2, bB3);
            }
            // full-k dot = lo + hi; fold into packed running maxes
            rmaxA = hmax2_u(rmaxA, hadd2_u(c0lo0, c0hi0));
            rmaxB = hmax2_u(rmaxB, hadd2_u(c0lo1, c0hi1));
            rmaxC = hmax2_u(rmaxC, hadd2_u(c1lo0, c1hi0));
            rmaxD = hmax2_u(rmaxD, hadd2_u(c1lo1, c1hi1));
        }
    }

    // ---- reduce: unpack, complete row maxes across the 4 lanes sharing g ----
    float m0 = hmax_final(rmaxA);   // row g
    float m1 = hmax_final(rmaxB);   // row g+8
    float m2 = hmax_final(rmaxC);   // row g+16
    float m3 = hmax_final(rmaxD);   // row g+24
    #pragma unroll
    for (int off = 1; off <= 2; off <<= 1) {
        m0 = fmaxf(m0, __shfl_xor_sync(0xffffffffu, m0, off));
        m1 = fmaxf(m1, __shfl_xor_sync(0xffffffffu, m1, off));
        m2 = fmaxf(m2, __shfl_xor_sync(0xffffffffu, m2, off));
        m3 = fmaxf(m3, __shfl_xor_sync(0xffffffffu, m3, off));
    }
    float v = m0 + m1 + m2 + m3;   // rows {g, g+8, g+16, g+24}
    v += __shfl_xor_sync(0xffffffffu, v, 4);
    v += __shfl_xor_sync(0xffffffffu, v, 8);
    v += __shfl_xor_sync(0xffffffffu, v, 16);

    if (lane == 0) {
        out[(qg * G_Q + w) * ND + c_doc] = v;
    }
}

extern "C" void kernel_launch(void* const* d_in, const int* in_sizes, int n_in,
                              void* d_out, int out_size) {
    const float* qs = (const float*)d_in[0];   // 64*32*128
    const float* ps = (const float*)d_in[1];   // 64*1024*128
    float* out = (float*)d_out;                // 64*64

    cvt_ps_kernel<<<(ND * TS * DIM / 8) / 256, 256>>>((const float4*)ps);

    dim3 grid(ND, NQ / G_Q);                   // (64 docs, 16 query groups)
    colbert_kernel<<<grid, THREADS>>>(qs, out);
}